// round 2
// baseline (speedup 1.0000x reference)
#include <cuda_runtime.h>
#include <math.h>

#define NN 50000
#define EE 500000
#define DD 64
#define GG 50
#define NPG 1000   // nodes per graph

// ---------------- scratch (static device globals; no runtime alloc) ----------------
__device__ __align__(16) float g_h   [NN*DD];
__device__ __align__(16) float g_h2  [NN*DD];
__device__ __align__(16) float g_a   [NN*DD];
__device__ __align__(16) float g_b   [NN*DD];
__device__ __align__(16) float g_aggr[NN*DD];
__device__ int   g_cnt[NN];
__device__ int   g_rowptr[NN+1];
__device__ int   g_csr_src[EE];
__device__ float g_csr_dist[EE];
__device__ __align__(16) float g_stats[DD+1];   // colsum[64], sumsq
__device__ __align__(16) float g_norm [DD+1];   // mu[64], 1/denom
__device__ int   g_bsum[256];

// ---------------- CSR build ----------------
__global__ void k_zero_cnt() {
    int i = blockIdx.x*blockDim.x + threadIdx.x;
    if (i < NN) g_cnt[i] = 0;
}

__global__ void k_count(const int* __restrict__ ei) {
    int e = blockIdx.x*blockDim.x + threadIdx.x;
    if (e < EE) atomicAdd(&g_cnt[ei[EE + e]], 1);
}

__global__ void k_scan1() {
    __shared__ int s[256];
    int tid = threadIdx.x;
    int i = blockIdx.x*256 + tid;
    int c = (i < NN) ? g_cnt[i] : 0;
    s[tid] = c;
    __syncthreads();
    #pragma unroll
    for (int off = 1; off < 256; off <<= 1) {
        int t = 0;
        if (tid >= off) t = s[tid - off];
        __syncthreads();
        s[tid] += t;
        __syncthreads();
    }
    if (i < NN) g_rowptr[i] = s[tid] - c;       // exclusive within block
    if (tid == 255) g_bsum[blockIdx.x] = s[255]; // block total
}

__global__ void k_scan2(int nb) {
    __shared__ int s[256];
    int tid = threadIdx.x;
    int c = (tid < nb) ? g_bsum[tid] : 0;
    s[tid] = c;
    __syncthreads();
    #pragma unroll
    for (int off = 1; off < 256; off <<= 1) {
        int t = 0;
        if (tid >= off) t = s[tid - off];
        __syncthreads();
        s[tid] += t;
        __syncthreads();
    }
    if (tid < nb) g_bsum[tid] = s[tid] - c;     // exclusive block offsets
}

__global__ void k_scan3() {
    int i = blockIdx.x*256 + threadIdx.x;
    if (i < NN) {
        int r = g_rowptr[i] + g_bsum[blockIdx.x];
        g_rowptr[i] = r;
        g_cnt[i] = r;   // cursor for fill
    }
    if (i == 0) g_rowptr[NN] = EE;
}

__global__ void k_fill(const int* __restrict__ ei, const float* __restrict__ pos) {
    int e = blockIdx.x*blockDim.x + threadIdx.x;
    if (e >= EE) return;
    int s = ei[e];
    int d = ei[EE + e];
    int p = atomicAdd(&g_cnt[d], 1);
    float dx = pos[2*d]   - pos[2*s];
    float dy = pos[2*d+1] - pos[2*s+1];
    g_csr_src[p]  = s;
    g_csr_dist[p] = sqrtf(dx*dx + dy*dy);
}

// ---------------- input embedding: h = relu(h_in @ Wemb + bemb) ----------------
__global__ void k_embed(const float* __restrict__ hin,
                        const float* __restrict__ W,
                        const float* __restrict__ b) {
    int w    = (blockIdx.x*blockDim.x + threadIdx.x) >> 5;
    int lane = threadIdx.x & 31;
    if (w >= NN) return;
    float v0 = hin[w*5+0], v1 = hin[w*5+1], v2 = hin[w*5+2],
          v3 = hin[w*5+3], v4 = hin[w*5+4];
    int c0 = lane*2;
    #pragma unroll
    for (int j = 0; j < 2; j++) {
        int c = c0 + j;
        float acc = b[c] + v0*W[c] + v1*W[64+c] + v2*W[128+c]
                         + v3*W[192+c] + v4*W[256+c];
        g_h[w*64+c] = fmaxf(acc, 0.f);
    }
}

// ---------------- GEMM: [a|b] = h @ Wm_remap  (N x 64 -> N x 128) ----------------
__global__ void __launch_bounds__(256) k_gemm_ab(const float* __restrict__ Wm) {
    __shared__ float sXT[32][129];
    __shared__ float sW [32][128];
    int tid  = threadIdx.x;
    int base = blockIdx.x * 128;
    int ng = tid & 15;     // node group: nodes ng + 16*i
    int cg = tid >> 4;     // col group : cols  cg*8 .. cg*8+7  (0..127)
    float acc[8][8];
    #pragma unroll
    for (int i = 0; i < 8; i++)
        #pragma unroll
        for (int j = 0; j < 8; j++) acc[i][j] = 0.f;

    for (int kc = 0; kc < 64; kc += 32) {
        __syncthreads();
        // stage X (transposed) : 128 nodes x 32 k
        #pragma unroll
        for (int it = 0; it < 4; it++) {
            int idx = tid + 256*it;
            int nl  = idx >> 3;
            int kq  = idx & 7;
            int n   = base + nl;
            float4 v = make_float4(0.f,0.f,0.f,0.f);
            if (n < NN) v = *(const float4*)&g_h[n*64 + kc + kq*4];
            sXT[kq*4+0][nl] = v.x;
            sXT[kq*4+1][nl] = v.y;
            sXT[kq*4+2][nl] = v.z;
            sXT[kq*4+3][nl] = v.w;
        }
        // stage W with remap: col c<64 -> Wm[kc+kk][c] ; c>=64 -> Wm[64+kc+kk][c-64]
        // 32 kk x 128 c = 4096 floats -> 16 iterations of 256 threads
        #pragma unroll
        for (int it = 0; it < 16; it++) {
            int idx = tid + 256*it;
            int c   = idx & 127;
            int kk  = idx >> 7;          // 0..31
            int row = (c < 64) ? (kc + kk) : (64 + kc + kk);
            sW[kk][c] = Wm[row*64 + (c & 63)];
        }
        __syncthreads();
        #pragma unroll
        for (int kk = 0; kk < 32; kk++) {
            float xv[8];
            #pragma unroll
            for (int i = 0; i < 8; i++) xv[i] = sXT[kk][ng + 16*i];
            float4 wA = *(const float4*)&sW[kk][cg*8];
            float4 wB = *(const float4*)&sW[kk][cg*8 + 4];
            float wv[8] = {wA.x,wA.y,wA.z,wA.w,wB.x,wB.y,wB.z,wB.w};
            #pragma unroll
            for (int i = 0; i < 8; i++)
                #pragma unroll
                for (int j = 0; j < 8; j++)
                    acc[i][j] = fmaf(xv[i], wv[j], acc[i][j]);
        }
    }
    float* Out = (cg < 8) ? g_a : g_b;
    int c0     = (cg < 8) ? cg*8 : cg*8 - 64;
    #pragma unroll
    for (int i = 0; i < 8; i++) {
        int n = base + ng + 16*i;
        if (n < NN) {
            *(float4*)&Out[n*64 + c0]     = make_float4(acc[i][0],acc[i][1],acc[i][2],acc[i][3]);
            *(float4*)&Out[n*64 + c0 + 4] = make_float4(acc[i][4],acc[i][5],acc[i][6],acc[i][7]);
        }
    }
}

// ---------------- per-node edge gather: aggr[i] = sum_e relu(a[i]+b[src]+d*wd+bm) ----------------
__global__ void k_gather(const float* __restrict__ Wm, const float* __restrict__ bm) {
    int gw   = (blockIdx.x*blockDim.x + threadIdx.x) >> 5;
    int lane = threadIdx.x & 31;
    if (gw >= NN) return;
    int c0 = lane*2;
    const float* wdrow = Wm + 128*64;   // row 128 = dist weights
    float wdx = wdrow[c0], wdy = wdrow[c0+1];
    float pax = g_a[gw*64+c0]   + bm[c0];
    float pay = g_a[gw*64+c0+1] + bm[c0+1];
    float ax = 0.f, ay = 0.f;
    int st = g_rowptr[gw], en = g_rowptr[gw+1];
    for (int e = st; e < en; e++) {
        int   s  = g_csr_src[e];
        float dd = g_csr_dist[e];
        float2 bv = *(const float2*)&g_b[s*64 + c0];
        ax += fmaxf(pax + bv.x + dd*wdx, 0.f);
        ay += fmaxf(pay + bv.y + dd*wdy, 0.f);
    }
    *(float2*)&g_aggr[gw*64 + c0] = make_float2(ax, ay);
}

__global__ void k_zero_stats() {
    int tid = threadIdx.x;
    if (tid < DD+1) g_stats[tid] = 0.f;
}

// ---------------- update GEMM: h2 = relu([h|aggr] @ Wu + bu), + pairnorm stats ----------------
__global__ void __launch_bounds__(256) k_gemm_upd(const float* __restrict__ Wu,
                                                  const float* __restrict__ bu) {
    __shared__ float sXT[32][129];
    __shared__ float sW [32][68];
    int tid  = threadIdx.x;
    int base = blockIdx.x * 128;
    int ng = tid & 15;
    int cg = tid >> 4;          // cols cg*4 .. cg*4+3 (0..63)
    float acc[8][4];
    #pragma unroll
    for (int i = 0; i < 8; i++)
        #pragma unroll
        for (int j = 0; j < 4; j++) acc[i][j] = 0.f;

    for (int kc = 0; kc < 128; kc += 32) {
        __syncthreads();
        const float* Xsrc = (kc < 64) ? g_h : g_aggr;
        int koff = kc & 63;
        #pragma unroll
        for (int it = 0; it < 4; it++) {
            int idx = tid + 256*it;
            int nl  = idx >> 3;
            int kq  = idx & 7;
            int n   = base + nl;
            float4 v = make_float4(0.f,0.f,0.f,0.f);
            if (n < NN) v = *(const float4*)&Xsrc[n*64 + koff + kq*4];
            sXT[kq*4+0][nl] = v.x;
            sXT[kq*4+1][nl] = v.y;
            sXT[kq*4+2][nl] = v.z;
            sXT[kq*4+3][nl] = v.w;
        }
        #pragma unroll
        for (int it = 0; it < 8; it++) {
            int idx = tid + 256*it;     // 2048 floats
            int c   = idx & 63;
            int kk  = idx >> 6;
            sW[kk][c] = Wu[(kc + kk)*64 + c];
        }
        __syncthreads();
        #pragma unroll
        for (int kk = 0; kk < 32; kk++) {
            float xv[8];
            #pragma unroll
            for (int i = 0; i < 8; i++) xv[i] = sXT[kk][ng + 16*i];
            float4 w = *(const float4*)&sW[kk][cg*4];
            float wv[4] = {w.x, w.y, w.z, w.w};
            #pragma unroll
            for (int i = 0; i < 8; i++)
                #pragma unroll
                for (int j = 0; j < 4; j++)
                    acc[i][j] = fmaf(xv[i], wv[j], acc[i][j]);
        }
    }
    int c0 = cg*4;
    float4 bb = *(const float4*)&bu[c0];
    float bvv[4] = {bb.x, bb.y, bb.z, bb.w};
    float ls[4] = {0.f,0.f,0.f,0.f};
    float lss = 0.f;
    #pragma unroll
    for (int i = 0; i < 8; i++) {
        int n = base + ng + 16*i;
        if (n < NN) {
            float o[4];
            #pragma unroll
            for (int j = 0; j < 4; j++) {
                o[j] = fmaxf(acc[i][j] + bvv[j], 0.f);
                ls[j] += o[j];
                lss   += o[j]*o[j];
            }
            *(float4*)&g_h2[n*64 + c0] = make_float4(o[0],o[1],o[2],o[3]);
        }
    }
    // reduce over the 16 lanes sharing this cg (width-16 segments)
    #pragma unroll
    for (int off = 8; off >= 1; off >>= 1) {
        #pragma unroll
        for (int j = 0; j < 4; j++)
            ls[j] += __shfl_down_sync(0xffffffffu, ls[j], off, 16);
        lss += __shfl_down_sync(0xffffffffu, lss, off, 16);
    }
    if ((tid & 15) == 0) {
        #pragma unroll
        for (int j = 0; j < 4; j++) atomicAdd(&g_stats[c0 + j], ls[j]);
        atomicAdd(&g_stats[64], lss);
    }
}

// ---------------- pairnorm finalize + apply ----------------
__global__ void k_normfin() {
    int tid = threadIdx.x;   // 64 threads
    __shared__ float sred[2];
    float mu = g_stats[tid] * (1.0f/NN);
    g_norm[tid] = mu;
    float m2 = mu*mu;
    #pragma unroll
    for (int off = 16; off > 0; off >>= 1)
        m2 += __shfl_down_sync(0xffffffffu, m2, off);
    if ((tid & 31) == 0) sred[tid >> 5] = m2;
    __syncthreads();
    if (tid == 0) {
        float musq  = sred[0] + sred[1];
        float denom = sqrtf(1e-5f + g_stats[64]*(1.0f/NN) - musq);
        g_norm[64]  = 1.0f / denom;
    }
}

__global__ void k_normalize() {
    int idx = blockIdx.x*blockDim.x + threadIdx.x;  // over NN*16 float4 groups
    if (idx >= NN*16) return;
    int c0 = (idx & 15) * 4;
    float  inv = g_norm[64];
    float4 mu  = *(const float4*)&g_norm[c0];
    float4 v   = *(const float4*)&g_h2[idx*4];
    float4 o;
    o.x = (v.x - mu.x)*inv;
    o.y = (v.y - mu.y)*inv;
    o.z = (v.z - mu.z)*inv;
    o.w = (v.w - mu.w)*inv;
    *(float4*)&g_h[idx*4] = o;
}

// ---------------- per-graph max pool + tiny MLP ----------------
__global__ void k_pool(const float* __restrict__ W1, const float* __restrict__ b1,
                       const float* __restrict__ W2, const float* __restrict__ b2,
                       float* __restrict__ out) {
    __shared__ float red[4][64];
    __shared__ float hg[64];
    __shared__ float z[64];
    int g   = blockIdx.x;
    int tid = threadIdx.x;
    int c     = tid & 63;
    int chunk = tid >> 6;           // 0..3
    float m = -3.4e38f;
    int nbeg = g*NPG + chunk*(NPG/4);
    for (int i = 0; i < NPG/4; i++)
        m = fmaxf(m, g_h[(nbeg + i)*64 + c]);
    red[chunk][c] = m;
    __syncthreads();
    if (tid < 64)
        hg[tid] = fmaxf(fmaxf(red[0][tid], red[1][tid]),
                        fmaxf(red[2][tid], red[3][tid]));
    __syncthreads();
    if (tid < 64) {
        float acc = b1[tid];
        for (int k = 0; k < 64; k++) acc = fmaf(hg[k], W1[k*64 + tid], acc);
        z[tid] = fmaxf(acc, 0.f);
    }
    __syncthreads();
    if (tid < 2) {
        float acc = b2[tid];
        for (int k = 0; k < 64; k++) acc = fmaf(z[k], W2[k*2 + tid], acc);
        out[g*2 + tid] = acc;
    }
}

// ---------------- launch ----------------
extern "C" void kernel_launch(void* const* d_in, const int* in_sizes, int n_in,
                              void* d_out, int out_size) {
    const float* h_in = (const float*)d_in[0];
    const float* pos  = (const float*)d_in[1];
    const int*   ei   = (const int*)  d_in[2];
    // d_in[3] = batch (contiguous 1000-node graphs; structure fixed) — unused
    const float* Wemb = (const float*)d_in[4];
    const float* bemb = (const float*)d_in[5];
    const float* msgW = (const float*)d_in[6];
    const float* msgb = (const float*)d_in[7];
    const float* updW = (const float*)d_in[8];
    const float* updb = (const float*)d_in[9];
    const float* W1   = (const float*)d_in[10];
    const float* b1   = (const float*)d_in[11];
    const float* W2   = (const float*)d_in[12];
    const float* b2   = (const float*)d_in[13];
    float* out = (float*)d_out;

    // CSR build (per launch; graph is an input)
    k_zero_cnt<<<196, 256>>>();
    k_count   <<<1954, 256>>>(ei);
    k_scan1   <<<196, 256>>>();
    k_scan2   <<<1, 256>>>(196);
    k_scan3   <<<196, 256>>>();
    k_fill    <<<1954, 256>>>(ei, pos);

    k_embed   <<<6250, 256>>>(h_in, Wemb, bemb);

    for (int l = 0; l < 2; l++) {
        const float* Wm = msgW + l*129*64;
        const float* bm = msgb + l*64;
        const float* Wu = updW + l*128*64;
        const float* bu = updb + l*64;
        k_gemm_ab   <<<391, 256>>>(Wm);
        k_gather    <<<6250, 256>>>(Wm, bm);
        k_zero_stats<<<1, 128>>>();
        k_gemm_upd  <<<391, 256>>>(Wu, bu);
        k_normfin   <<<1, 64>>>();
        k_normalize <<<3125, 256>>>();
    }

    k_pool<<<50, 256>>>(W1, b1, W2, b2, out);
}